// round 5
// baseline (speedup 1.0000x reference)
#include <cuda_runtime.h>

#define N_NODES 100000
#define E_EDGES 500000
#define H 128

// Precomputed per-node MLP partials (b1 folded into the dst half):
//   C_x[row][0:128]   = z_x[row] @ w1[0:128, :]          (src contribution)
//   C_x[row][128:256] = z_x[row] @ w1[128:256, :] + b1   (dst contribution)
__device__ float g_Cp[(size_t)N_NODES * 256];
__device__ float g_Co[(size_t)N_NODES * 256];

#define ASTRIDE 132                    // padded A row (floats)
#define A_BUF   (32 * ASTRIDE)         // 4224 floats per stage
#define B_BUF   (32 * 256)             // 8192 floats per stage
#define SMEM_FLOATS (2 * A_BUF + 2 * B_BUF)   // 24832 floats = 99328 B

__device__ __forceinline__ void cp_async16(float* smem_dst, const float* gmem_src) {
    unsigned sa = (unsigned)__cvta_generic_to_shared(smem_dst);
    asm volatile("cp.async.cg.shared.global [%0], [%1], 16;\n" :: "r"(sa), "l"(gmem_src));
}
__device__ __forceinline__ void cp_commit() { asm volatile("cp.async.commit_group;\n"); }
__device__ __forceinline__ void cp_wait0()  { asm volatile("cp.async.wait_group 0;\n"); }

// ---------------------------------------------------------------------------
// Phase 1: merged node GEMM.  grid = (ceil(M/128), 2 tables), 256 threads.
// Tile: 128m x 256n (both w1 halves share one A tile), K = 128 in 4 x 32.
// Per thread: 8m x 16n = 128 accumulators; 96B smem per 128 FMA -> FMA-bound.
// Double-buffered: B via cp.async, A reg-staged (transposed store).
// ---------------------------------------------------------------------------
__global__ __launch_bounds__(256, 1)
void node_gemm_kernel(const float* __restrict__ Zp,
                      const float* __restrict__ Zo,
                      const float* __restrict__ w1,
                      const float* __restrict__ b1)
{
    extern __shared__ float smem[];
    float* As[2] = { smem,              smem + A_BUF };
    float* Bs[2] = { smem + 2 * A_BUF,  smem + 2 * A_BUF + B_BUF };

    const int table = blockIdx.y;
    const float* __restrict__ Z = table ? Zo : Zp;
    float* __restrict__ C       = table ? g_Co : g_Cp;

    const int tid = threadIdx.x;
    const int tx  = tid & 15;        // n-group (16)
    const int ty  = tid >> 4;        // m-group (16)
    const int m0  = blockIdx.x * 128;

    // ---- per-thread A/B load coordinates (compile-time per i) ----
    // A: 1024 float4 slots: row = f4>>3 (0..127), c4 = f4&7 (k float4)
    // B: 2048 float4 slots: k = f4>>6 (0..31), n4 = f4&63; n4<32 -> part0 row,
    //    n4>=32 -> part1 row (w1 row 128+kk+k).

    float4 areg[4];

    // ---------- prologue: chunk 0 ----------
    {
        const int kk = 0;
#pragma unroll
        for (int i = 0; i < 8; i++) {
            int f4 = tid + 256 * i;
            int k  = f4 >> 6;
            int n4 = f4 & 63;
            const float* src = (n4 < 32)
                ? &w1[(size_t)(kk + k) * H + n4 * 4]
                : &w1[(size_t)(128 + kk + k) * H + (n4 - 32) * 4];
            cp_async16(&Bs[0][k * 256 + n4 * 4], src);
        }
        cp_commit();
#pragma unroll
        for (int i = 0; i < 4; i++) {
            int f4  = tid + 256 * i;
            int row = f4 >> 3;
            int c4  = f4 & 7;
            areg[i] = (m0 + row < N_NODES)
                ? *(const float4*)&Z[(size_t)(m0 + row) * H + kk + c4 * 4]
                : make_float4(0.f, 0.f, 0.f, 0.f);
        }
#pragma unroll
        for (int i = 0; i < 4; i++) {
            int f4  = tid + 256 * i;
            int row = f4 >> 3;
            int c4  = f4 & 7;
            As[0][(c4 * 4 + 0) * ASTRIDE + row] = areg[i].x;
            As[0][(c4 * 4 + 1) * ASTRIDE + row] = areg[i].y;
            As[0][(c4 * 4 + 2) * ASTRIDE + row] = areg[i].z;
            As[0][(c4 * 4 + 3) * ASTRIDE + row] = areg[i].w;
        }
        cp_wait0();
        __syncthreads();
    }

    float acc[2][4][4][4];   // [mgroup][nquad][mrow][ncol]
#pragma unroll
    for (int mg = 0; mg < 2; mg++)
#pragma unroll
        for (int q = 0; q < 4; q++)
#pragma unroll
            for (int r = 0; r < 4; r++)
#pragma unroll
                for (int c = 0; c < 4; c++)
                    acc[mg][q][r][c] = 0.f;

    // ---------- main loop over 4 k-chunks ----------
#pragma unroll
    for (int ch = 0; ch < 4; ch++) {
        const int cur = ch & 1;
        const int nxt = cur ^ 1;

        if (ch < 3) {
            const int kk = (ch + 1) * 32;
#pragma unroll
            for (int i = 0; i < 8; i++) {
                int f4 = tid + 256 * i;
                int k  = f4 >> 6;
                int n4 = f4 & 63;
                const float* src = (n4 < 32)
                    ? &w1[(size_t)(kk + k) * H + n4 * 4]
                    : &w1[(size_t)(128 + kk + k) * H + (n4 - 32) * 4];
                cp_async16(&Bs[nxt][k * 256 + n4 * 4], src);
            }
            cp_commit();
#pragma unroll
            for (int i = 0; i < 4; i++) {
                int f4  = tid + 256 * i;
                int row = f4 >> 3;
                int c4  = f4 & 7;
                areg[i] = (m0 + row < N_NODES)
                    ? *(const float4*)&Z[(size_t)(m0 + row) * H + kk + c4 * 4]
                    : make_float4(0.f, 0.f, 0.f, 0.f);
            }
        }

        const float* __restrict__ A = As[cur];
        const float* __restrict__ B = Bs[cur];
#pragma unroll
        for (int k = 0; k < 32; k++) {
            float4 a0 = *(const float4*)&A[k * ASTRIDE + ty * 4];
            float4 a1 = *(const float4*)&A[k * ASTRIDE + ty * 4 + 64];
            float4 bq[4];
#pragma unroll
            for (int q = 0; q < 4; q++)
                bq[q] = *(const float4*)&B[k * 256 + tx * 4 + q * 64];

            float am[2][4] = {{a0.x, a0.y, a0.z, a0.w}, {a1.x, a1.y, a1.z, a1.w}};
#pragma unroll
            for (int mg = 0; mg < 2; mg++)
#pragma unroll
                for (int q = 0; q < 4; q++)
#pragma unroll
                    for (int r = 0; r < 4; r++) {
                        acc[mg][q][r][0] = fmaf(am[mg][r], bq[q].x, acc[mg][q][r][0]);
                        acc[mg][q][r][1] = fmaf(am[mg][r], bq[q].y, acc[mg][q][r][1]);
                        acc[mg][q][r][2] = fmaf(am[mg][r], bq[q].z, acc[mg][q][r][2]);
                        acc[mg][q][r][3] = fmaf(am[mg][r], bq[q].w, acc[mg][q][r][3]);
                    }
        }

        if (ch < 3) {
#pragma unroll
            for (int i = 0; i < 4; i++) {
                int f4  = tid + 256 * i;
                int row = f4 >> 3;
                int c4  = f4 & 7;
                As[nxt][(c4 * 4 + 0) * ASTRIDE + row] = areg[i].x;
                As[nxt][(c4 * 4 + 1) * ASTRIDE + row] = areg[i].y;
                As[nxt][(c4 * 4 + 2) * ASTRIDE + row] = areg[i].z;
                As[nxt][(c4 * 4 + 3) * ASTRIDE + row] = areg[i].w;
            }
            cp_wait0();
        }
        __syncthreads();
    }

    // ---------- store (fold b1 into columns 128:256) ----------
#pragma unroll
    for (int mg = 0; mg < 2; mg++) {
#pragma unroll
        for (int r = 0; r < 4; r++) {
            int row = m0 + ty * 4 + mg * 64 + r;
            if (row < N_NODES) {
#pragma unroll
                for (int q = 0; q < 4; q++) {
                    int n = tx * 4 + q * 64;
                    float4 v = make_float4(acc[mg][q][r][0], acc[mg][q][r][1],
                                           acc[mg][q][r][2], acc[mg][q][r][3]);
                    if (n >= 128) {
                        float4 bb = __ldg((const float4*)&b1[n - 128]);
                        v.x += bb.x; v.y += bb.y; v.z += bb.z; v.w += bb.w;
                    }
                    *(float4*)&C[(size_t)row * 256 + n] = v;
                }
            }
        }
    }
}

// ---------------------------------------------------------------------------
// Phase 2: per-edge gather + relu + dot(w2).  TWO edges per warp (2-way ILP
// hides gather + shuffle latency).  grid = (E/16, 3), 256 threads.
// ---------------------------------------------------------------------------
__global__ __launch_bounds__(256)
void edge_kernel(const int* __restrict__ ptnp,
                 const int* __restrict__ nptp,
                 const int* __restrict__ nptnp,
                 const float* __restrict__ w2,
                 const float* __restrict__ b2,
                 float* __restrict__ out)
{
    const int warp = blockIdx.x * 8 + (threadIdx.x >> 5);
    const int lane = threadIdx.x & 31;
    const int i0   = warp * 2;
    if (i0 >= E_EDGES) return;
    const int type = blockIdx.y;

    const float* __restrict__ src_tab;
    const float* __restrict__ dst_tab;
    const int* __restrict__ idx;
    if (type == 0) {            // ptnp: pnode -> onode
        idx = ptnp;  src_tab = g_Cp; dst_tab = g_Co;
    } else if (type == 1) {     // nptp: onode -> pnode
        idx = nptp;  src_tab = g_Co; dst_tab = g_Cp;
    } else {                    // nptnp: onode -> onode
        idx = nptnp; src_tab = g_Co; dst_tab = g_Co;
    }

    const int s0 = __ldg(&idx[i0]);
    const int s1 = __ldg(&idx[i0 + 1]);
    const int d0 = __ldg(&idx[E_EDGES + i0]);
    const int d1 = __ldg(&idx[E_EDGES + i0 + 1]);

    const float4 wv = __ldg((const float4*)w2 + lane);

    const float4 sv0 = *(const float4*)(src_tab + (size_t)s0 * 256 + lane * 4);
    const float4 dv0 = *(const float4*)(dst_tab + (size_t)d0 * 256 + 128 + lane * 4);
    const float4 sv1 = *(const float4*)(src_tab + (size_t)s1 * 256 + lane * 4);
    const float4 dv1 = *(const float4*)(dst_tab + (size_t)d1 * 256 + 128 + lane * 4);

    float sum0, sum1;
    {
        float h0 = fmaxf(sv0.x + dv0.x, 0.f);
        float h1 = fmaxf(sv0.y + dv0.y, 0.f);
        float h2 = fmaxf(sv0.z + dv0.z, 0.f);
        float h3 = fmaxf(sv0.w + dv0.w, 0.f);
        sum0 = h0 * wv.x + h1 * wv.y + h2 * wv.z + h3 * wv.w;
    }
    {
        float h0 = fmaxf(sv1.x + dv1.x, 0.f);
        float h1 = fmaxf(sv1.y + dv1.y, 0.f);
        float h2 = fmaxf(sv1.z + dv1.z, 0.f);
        float h3 = fmaxf(sv1.w + dv1.w, 0.f);
        sum1 = h0 * wv.x + h1 * wv.y + h2 * wv.z + h3 * wv.w;
    }

#pragma unroll
    for (int o = 16; o; o >>= 1) {
        sum0 += __shfl_xor_sync(0xffffffffu, sum0, o);
        sum1 += __shfl_xor_sync(0xffffffffu, sum1, o);
    }

    if (lane == 0) {
        const float bias2 = __ldg(b2);
        float2 res = make_float2(sum0 + bias2, sum1 + bias2);
        *(float2*)&out[(size_t)type * E_EDGES + i0] = res;
    }
}

// ---------------------------------------------------------------------------
extern "C" void kernel_launch(void* const* d_in, const int* in_sizes, int n_in,
                              void* d_out, int out_size)
{
    const float* zp    = (const float*)d_in[0];
    const float* zo    = (const float*)d_in[1];
    const int*   ptnp  = (const int*)d_in[2];
    const int*   nptp  = (const int*)d_in[3];
    const int*   nptnp = (const int*)d_in[4];
    const float* w1    = (const float*)d_in[5];
    const float* b1    = (const float*)d_in[6];
    const float* w2    = (const float*)d_in[7];
    const float* b2    = (const float*)d_in[8];
    float* out = (float*)d_out;

    const int smem_bytes = SMEM_FLOATS * sizeof(float);   // 99328
    cudaFuncSetAttribute(node_gemm_kernel,
                         cudaFuncAttributeMaxDynamicSharedMemorySize, smem_bytes);

    dim3 g1((N_NODES + 127) / 128, 2, 1);
    node_gemm_kernel<<<g1, 256, smem_bytes>>>(zp, zo, w1, b1);

    dim3 g2(E_EDGES / 16, 3, 1);
    edge_kernel<<<g2, 256>>>(ptnp, nptp, nptnp, w2, b2, out);
}

// round 6
// speedup vs baseline: 1.9130x; 1.9130x over previous
#include <cuda_runtime.h>

#define N_NODES 100000
#define E_EDGES 500000
#define H 128

// Precomputed per-node MLP partials (b1 folded into the dst half):
//   C_x[row][0:128]   = z_x[row] @ w1[0:128, :]          (src contribution)
//   C_x[row][128:256] = z_x[row] @ w1[128:256, :] + b1   (dst contribution)
__device__ float g_Cp[(size_t)N_NODES * 256];
__device__ float g_Co[(size_t)N_NODES * 256];

// ---------------------------------------------------------------------------
// Phase 1: node GEMMs.  grid = (ceil(M/128), 4), 256 threads.
// blockIdx.y: bit0 = w1 half (part), bit1 = table (0: pnode, 1: onode).
// Classic 128x128 fp32 register-blocked SGEMM, K = 128 in 4 chunks of 32.
// (Proven-good R0 structure; only change: b1 folded into part-1 store.)
// ---------------------------------------------------------------------------
__global__ __launch_bounds__(256, 2)
void node_gemm_kernel(const float* __restrict__ Zp,
                      const float* __restrict__ Zo,
                      const float* __restrict__ w1,
                      const float* __restrict__ b1)
{
    const int part  = blockIdx.y & 1;   // which half of w1
    const int table = blockIdx.y >> 1;  // 0: pnode, 1: onode
    const float* __restrict__ Z = table ? Zo : Zp;
    float* __restrict__ C       = table ? g_Co : g_Cp;
    const float* __restrict__ W = w1 + (size_t)part * 128 * H;  // [128][128] row-major

    __shared__ float As[32][132];   // A^T tile: [k][m], padded
    __shared__ float Bs[32][128];   // B tile:   [k][n]

    const int tid = threadIdx.x;
    const int tx  = tid & 15;       // n-group
    const int ty  = tid >> 4;       // m-group
    const int m0  = blockIdx.x * 128;

    float acc[2][2][4][4];
#pragma unroll
    for (int a = 0; a < 2; a++)
#pragma unroll
        for (int b = 0; b < 2; b++)
#pragma unroll
            for (int r = 0; r < 4; r++)
#pragma unroll
                for (int c = 0; c < 4; c++)
                    acc[a][b][r][c] = 0.f;

    for (int kk = 0; kk < H; kk += 32) {
        // Load A tile (128 rows x 32 k) transposed into As[k][m]
#pragma unroll
        for (int i = 0; i < 4; i++) {
            int f4  = tid + 256 * i;        // 0..1023 float4 slots
            int row = f4 >> 3;              // 0..127
            int c4  = f4 & 7;               // 0..7 (k float4 within chunk)
            float4 v = make_float4(0.f, 0.f, 0.f, 0.f);
            if (m0 + row < N_NODES)
                v = *(const float4*)&Z[(size_t)(m0 + row) * H + kk + c4 * 4];
            As[c4 * 4 + 0][row] = v.x;
            As[c4 * 4 + 1][row] = v.y;
            As[c4 * 4 + 2][row] = v.z;
            As[c4 * 4 + 3][row] = v.w;
        }
        // Load B tile (32 k x 128 n)
#pragma unroll
        for (int i = 0; i < 4; i++) {
            int f4 = tid + 256 * i;         // 0..1023
            int k  = f4 >> 5;               // 0..31
            int n  = (f4 & 31) * 4;
            *(float4*)&Bs[k][n] = *(const float4*)&W[(size_t)(kk + k) * H + n];
        }
        __syncthreads();

#pragma unroll
        for (int k = 0; k < 32; k++) {
            float4 a0 = *(float4*)&As[k][ty * 4];
            float4 a1 = *(float4*)&As[k][ty * 4 + 64];
            float4 b0 = *(float4*)&Bs[k][tx * 4];
            float4 b1r = *(float4*)&Bs[k][tx * 4 + 64];
            float ar[2][4] = {{a0.x, a0.y, a0.z, a0.w}, {a1.x, a1.y, a1.z, a1.w}};
            float br[2][4] = {{b0.x, b0.y, b0.z, b0.w}, {b1r.x, b1r.y, b1r.z, b1r.w}};
#pragma unroll
            for (int im = 0; im < 2; im++)
#pragma unroll
                for (int r = 0; r < 4; r++)
#pragma unroll
                    for (int in = 0; in < 2; in++)
#pragma unroll
                        for (int c = 0; c < 4; c++)
                            acc[im][in][r][c] = fmaf(ar[im][r], br[in][c], acc[im][in][r][c]);
        }
        __syncthreads();
    }

    // Store: C[row][part*128 + n]; fold b1 into the dst half (part == 1)
#pragma unroll
    for (int im = 0; im < 2; im++) {
#pragma unroll
        for (int r = 0; r < 4; r++) {
            int row = m0 + ty * 4 + r + im * 64;
            if (row < N_NODES) {
#pragma unroll
                for (int in = 0; in < 2; in++) {
                    int n = tx * 4 + in * 64;
                    float4 v = make_float4(acc[im][in][r][0], acc[im][in][r][1],
                                           acc[im][in][r][2], acc[im][in][r][3]);
                    if (part == 1) {
                        float4 bb = __ldg((const float4*)&b1[n]);
                        v.x += bb.x; v.y += bb.y; v.z += bb.z; v.w += bb.w;
                    }
                    *(float4*)&C[(size_t)row * 256 + part * 128 + n] = v;
                }
            }
        }
    }
}

// ---------------------------------------------------------------------------
// Phase 2: per-edge gather + relu + dot(w2).  TWO edges per warp (2-way ILP
// hides gather + shuffle latency).  grid = (E/16, 3), 256 threads.
// (Unchanged from R5: measured 145 us.)
// ---------------------------------------------------------------------------
__global__ __launch_bounds__(256)
void edge_kernel(const int* __restrict__ ptnp,
                 const int* __restrict__ nptp,
                 const int* __restrict__ nptnp,
                 const float* __restrict__ w2,
                 const float* __restrict__ b2,
                 float* __restrict__ out)
{
    const int warp = blockIdx.x * 8 + (threadIdx.x >> 5);
    const int lane = threadIdx.x & 31;
    const int i0   = warp * 2;
    if (i0 >= E_EDGES) return;
    const int type = blockIdx.y;

    const float* __restrict__ src_tab;
    const float* __restrict__ dst_tab;
    const int* __restrict__ idx;
    if (type == 0) {            // ptnp: pnode -> onode
        idx = ptnp;  src_tab = g_Cp; dst_tab = g_Co;
    } else if (type == 1) {     // nptp: onode -> pnode
        idx = nptp;  src_tab = g_Co; dst_tab = g_Cp;
    } else {                    // nptnp: onode -> onode
        idx = nptnp; src_tab = g_Co; dst_tab = g_Co;
    }

    const int s0 = __ldg(&idx[i0]);
    const int s1 = __ldg(&idx[i0 + 1]);
    const int d0 = __ldg(&idx[E_EDGES + i0]);
    const int d1 = __ldg(&idx[E_EDGES + i0 + 1]);

    const float4 wv = __ldg((const float4*)w2 + lane);

    const float4 sv0 = *(const float4*)(src_tab + (size_t)s0 * 256 + lane * 4);
    const float4 dv0 = *(const float4*)(dst_tab + (size_t)d0 * 256 + 128 + lane * 4);
    const float4 sv1 = *(const float4*)(src_tab + (size_t)s1 * 256 + lane * 4);
    const float4 dv1 = *(const float4*)(dst_tab + (size_t)d1 * 256 + 128 + lane * 4);

    float sum0, sum1;
    {
        float h0 = fmaxf(sv0.x + dv0.x, 0.f);
        float h1 = fmaxf(sv0.y + dv0.y, 0.f);
        float h2 = fmaxf(sv0.z + dv0.z, 0.f);
        float h3 = fmaxf(sv0.w + dv0.w, 0.f);
        sum0 = h0 * wv.x + h1 * wv.y + h2 * wv.z + h3 * wv.w;
    }
    {
        float h0 = fmaxf(sv1.x + dv1.x, 0.f);
        float h1 = fmaxf(sv1.y + dv1.y, 0.f);
        float h2 = fmaxf(sv1.z + dv1.z, 0.f);
        float h3 = fmaxf(sv1.w + dv1.w, 0.f);
        sum1 = h0 * wv.x + h1 * wv.y + h2 * wv.z + h3 * wv.w;
    }

#pragma unroll
    for (int o = 16; o; o >>= 1) {
        sum0 += __shfl_xor_sync(0xffffffffu, sum0, o);
        sum1 += __shfl_xor_sync(0xffffffffu, sum1, o);
    }

    if (lane == 0) {
        const float bias2 = __ldg(b2);
        float2 res = make_float2(sum0 + bias2, sum1 + bias2);
        *(float2*)&out[(size_t)type * E_EDGES + i0] = res;
    }
}

// ---------------------------------------------------------------------------
extern "C" void kernel_launch(void* const* d_in, const int* in_sizes, int n_in,
                              void* d_out, int out_size)
{
    const float* zp    = (const float*)d_in[0];
    const float* zo    = (const float*)d_in[1];
    const int*   ptnp  = (const int*)d_in[2];
    const int*   nptp  = (const int*)d_in[3];
    const int*   nptnp = (const int*)d_in[4];
    const float* w1    = (const float*)d_in[5];
    const float* b1    = (const float*)d_in[6];
    const float* w2    = (const float*)d_in[7];
    const float* b2    = (const float*)d_in[8];
    float* out = (float*)d_out;

    dim3 g1((N_NODES + 127) / 128, 4, 1);
    node_gemm_kernel<<<g1, 256>>>(zp, zo, w1, b1);

    dim3 g2(E_EDGES / 16, 3, 1);
    edge_kernel<<<g2, 256>>>(ptnp, nptp, nptnp, w2, b2, out);
}